// round 15
// baseline (speedup 1.0000x reference)
#include <cuda_runtime.h>
#include <cuda_fp16.h>

// ---------------- problem constants ----------------
#define N_NODES  50000
#define N_EDGES  640000
#define N_GRAPHS 64
#define IN_DIM   128
#define HID      256
#define HID2     128   // HID/2
#define OUT_DIM  4

#define SCAN_TPB   256
#define SCAN_BLKS  ((N_NODES + SCAN_TPB - 1) / SCAN_TPB)   // 196

// ---------------- scratch (static device arrays; no allocation) ----------------
// RULE: symbols referenced ONLY inside device code (host shadow + ATS trap).
__device__ float              g_dinv[N_NODES];            // rsqrt(deg+1)
__device__ int                g_count [N_NODES];
__device__ int                g_rowptr[N_NODES + 1];
__device__ unsigned long long g_lb[SCAN_BLKS];            // lookback: state<<32 | sum
__device__ int                g_esrc [N_EDGES];
__device__ int                g_eoff [N_EDGES];
__device__ float              g_enorm[N_EDGES];
__device__ unsigned short     g_xh  [N_NODES * IN_DIM];   // x as fp16
__device__ unsigned short     g_w1h [HID  * IN_DIM];      // W1^T [256][128] fp16
__device__ unsigned short     g_w2h [HID2 * HID];         // W2^T [128][256] fp16
__device__ unsigned short     g_a1h [N_NODES * IN_DIM];   // aggregated x, fp16
__device__ unsigned short     g_h1h [N_NODES * HID];      // relu(a1@W1+b1), fp16
__device__ unsigned short     g_m2h [N_NODES * HID2];     // h1@W2, fp16
__device__ float              g_pool[N_GRAPHS * HID2];
__device__ float              g_cnt [N_GRAPHS];
__device__ int                g_idx64;

// ---------------- helpers ----------------
__device__ __forceinline__ void red_add_v4(float* addr, float4 v) {
    asm volatile("red.global.add.v4.f32 [%0], {%1,%2,%3,%4};"
                 :: "l"(addr), "f"(v.x), "f"(v.y), "f"(v.z), "f"(v.w)
                 : "memory");
}

__device__ __forceinline__ int get_idx(const void* p, int i, int is64) {
    long long v;
    if (is64) v = __ldg(((const long long*)p) + i);
    else      v = __ldg(((const int*)p) + i);
    return (int)v;
}

// m16n8k16 fp16 MMA, fp32 accumulate (D += A*B), row.col
__device__ __forceinline__ void mma_f16(float* d, const unsigned* a, const unsigned* b) {
    asm volatile(
        "mma.sync.aligned.m16n8k16.row.col.f32.f16.f16.f32 "
        "{%0,%1,%2,%3}, {%4,%5,%6,%7}, {%8,%9}, {%0,%1,%2,%3};"
        : "+f"(d[0]), "+f"(d[1]), "+f"(d[2]), "+f"(d[3])
        : "r"(a[0]), "r"(a[1]), "r"(a[2]), "r"(a[3]), "r"(b[0]), "r"(b[1]));
}

__device__ __forceinline__ void ldsm_x4(unsigned* r, const void* smem_addr) {
    unsigned a = (unsigned)__cvta_generic_to_shared(smem_addr);
    asm volatile("ldmatrix.sync.aligned.m8n8.x4.shared.b16 {%0,%1,%2,%3}, [%4];"
                 : "=r"(r[0]), "=r"(r[1]), "=r"(r[2]), "=r"(r[3]) : "r"(a));
}

__device__ __forceinline__ void cp_async16(void* smem, const void* gmem, int szbytes) {
    unsigned saddr = (unsigned)__cvta_generic_to_shared(smem);
    asm volatile("cp.async.cg.shared.global [%0], [%1], 16, %2;"
                 :: "r"(saddr), "l"(gmem), "r"(szbytes));
}
__device__ __forceinline__ void cp_commit() {
    asm volatile("cp.async.commit_group;");
}
template <int N>
__device__ __forceinline__ void cp_wait() {
    asm volatile("cp.async.wait_group %0;" :: "n"(N));
}

__device__ __forceinline__ float2 h2f(unsigned u) {
    __half2 h = *reinterpret_cast<__half2*>(&u);
    return __half22float2(h);
}
__device__ __forceinline__ unsigned f2h2(float a, float b) {
    __half2 h = __floats2half2_rn(a, b);
    return *reinterpret_cast<unsigned*>(&h);
}

// ---------------- fused setup: detect dtype, cvt x + weights, zero ----------
__global__ void k_setup(const int* __restrict__ srcprobe, const float* __restrict__ x,
                        const float* __restrict__ W1, const float* __restrict__ W2) {
    int tid = blockIdx.x * blockDim.x + threadIdx.x;
    int nth = gridDim.x * blockDim.x;

    for (int i = tid; i < N_NODES * IN_DIM / 4; i += nth) {
        float4 v = ((const float4*)x)[i];
        uint2 o = make_uint2(f2h2(v.x, v.y), f2h2(v.z, v.w));
        ((uint2*)g_xh)[i] = o;
    }
    for (int i = tid; i < IN_DIM * HID; i += nth) {
        int n = i >> 7, k = i & 127;
        g_w1h[n * IN_DIM + k] = __half_as_ushort(__float2half_rn(W1[k * HID + n]));
    }
    for (int i = tid; i < HID * HID2; i += nth) {
        int n = i >> 8, k = i & 255;
        g_w2h[n * HID + k] = __half_as_ushort(__float2half_rn(W2[k * HID2 + n]));
    }
    if (tid < N_NODES) g_count[tid] = 0;
    if (tid < SCAN_BLKS) g_lb[tid] = 0ull;
    if (tid < N_GRAPHS * HID2) g_pool[tid] = 0.0f;
    if (tid < N_GRAPHS) g_cnt[tid] = 0.0f;
    if (blockIdx.x == 0 && threadIdx.x < 32) {
        int lane = threadIdx.x;
        int nz = 0;
        for (int k = lane; k < 4096; k += 32)
            if (srcprobe[2 * k + 1] != 0) nz = 1;
        unsigned m = __ballot_sync(0xffffffffu, nz);
        if (lane == 0) g_idx64 = (m == 0u) ? 1 : 0;
    }
}

// ---------------- CSR build ----------------
__global__ void k_hist(const void* __restrict__ dst) {
    int e = blockIdx.x * blockDim.x + threadIdx.x;
    if (e < N_EDGES) {
        int d = get_idx(dst, e, g_idx64);
        if ((unsigned)d < (unsigned)N_NODES)
            g_eoff[e] = atomicAdd(&g_count[d], 1);
    }
}

// single-kernel decoupled-lookback scan -> rowptr, dinv
__global__ void __launch_bounds__(SCAN_TPB) k_scan() {
    __shared__ int sh[SCAN_TPB];
    __shared__ int s_excl;
    int b = blockIdx.x;
    int t = threadIdx.x;
    int i = b * SCAN_TPB + t;
    int c = (i < N_NODES) ? g_count[i] : 0;
    sh[t] = c;
    __syncthreads();
    for (int d = 1; d < SCAN_TPB; d <<= 1) {
        int u = (t >= d) ? sh[t - d] : 0;
        __syncthreads();
        sh[t] += u;
        __syncthreads();
    }
    int aggregate = sh[SCAN_TPB - 1];
    if (t == 0) {
        if (b == 0) {
            atomicExch(&g_lb[0], (2ull << 32) | (unsigned)aggregate);
            s_excl = 0;
        } else {
            atomicExch(&g_lb[b], (1ull << 32) | (unsigned)aggregate);
            int excl = 0;
            for (int j = b - 1; j >= 0; j--) {
                unsigned long long v;
                do { v = atomicAdd(&g_lb[j], 0ull); } while ((v >> 32) == 0ull);
                excl += (int)(unsigned)v;
                if ((v >> 32) == 2ull) break;
            }
            atomicExch(&g_lb[b], (2ull << 32) | (unsigned)(excl + aggregate));
            s_excl = excl;
        }
    }
    __syncthreads();
    if (i < N_NODES) {
        g_rowptr[i] = s_excl + sh[t] - c;
        g_dinv[i]   = rsqrtf((float)c + 1.0f);
    }
    if (b == 0 && t == 0) g_rowptr[N_NODES] = N_EDGES;
}

__global__ void k_fill(const void* __restrict__ src, const void* __restrict__ dst) {
    int e = blockIdx.x * blockDim.x + threadIdx.x;
    if (e >= N_EDGES) return;
    int is64 = g_idx64;
    int s = get_idx(src, e, is64);
    int d = get_idx(dst, e, is64);
    if ((unsigned)s >= (unsigned)N_NODES || (unsigned)d >= (unsigned)N_NODES) return;
    int pos = g_rowptr[d] + g_eoff[e];
    g_esrc [pos] = s;
    g_enorm[pos] = g_dinv[s] * g_dinv[d];
}

// ---------------- gather core (fp16 feature table, fp32 accumulate) --------
__device__ __forceinline__ float4 gather_acc(const uint2* __restrict__ ft, int wid, int j) {
    float di = g_dinv[wid];
    float s2 = di * di;
    uint2 u0 = ft[(size_t)wid * 32 + j];
    float2 p0 = h2f(u0.x), p1 = h2f(u0.y);
    float4 acc = make_float4(p0.x * s2, p0.y * s2, p1.x * s2, p1.y * s2);

    int i   = g_rowptr[wid];
    int end = g_rowptr[wid + 1];
    for (; i + 1 < end; i += 2) {
        int   s0 = __ldg(&g_esrc[i]),  s1 = __ldg(&g_esrc[i + 1]);
        float w0 = __ldg(&g_enorm[i]), w1 = __ldg(&g_enorm[i + 1]);
        uint2 ua = ft[(size_t)s0 * 32 + j];
        uint2 ub = ft[(size_t)s1 * 32 + j];
        float2 a0 = h2f(ua.x), a1 = h2f(ua.y);
        float2 b0 = h2f(ub.x), b1 = h2f(ub.y);
        acc.x += w0 * a0.x + w1 * b0.x;
        acc.y += w0 * a0.y + w1 * b0.y;
        acc.z += w0 * a1.x + w1 * b1.x;
        acc.w += w0 * a1.y + w1 * b1.y;
    }
    if (i < end) {
        int   s0 = __ldg(&g_esrc[i]);
        float w0 = __ldg(&g_enorm[i]);
        uint2 ua = ft[(size_t)s0 * 32 + j];
        float2 a0 = h2f(ua.x), a1 = h2f(ua.y);
        acc.x += w0 * a0.x; acc.y += w0 * a0.y;
        acc.z += w0 * a1.x; acc.w += w0 * a1.y;
    }
    return acc;
}

__global__ void k_gather1() {
    int wid = (blockIdx.x * blockDim.x + threadIdx.x) >> 5;
    if (wid >= N_NODES) return;
    int j = threadIdx.x & 31;
    float4 acc = gather_acc((const uint2*)g_xh, wid, j);
    ((uint2*)g_a1h)[(size_t)wid * 32 + j] =
        make_uint2(f2h2(acc.x, acc.y), f2h2(acc.z, acc.w));
}

__global__ void k_gather2(const void* __restrict__ batch, const float* __restrict__ b2) {
    int wid = (blockIdx.x * blockDim.x + threadIdx.x) >> 5;
    if (wid >= N_NODES) return;
    int j = threadIdx.x & 31;
    float4 acc = gather_acc((const uint2*)g_m2h, wid, j);

    int b = get_idx(batch, wid, g_idx64);
    if ((unsigned)b >= (unsigned)N_GRAPHS) return;
    float4 bb = ((const float4*)b2)[j];
    acc.x = fmaxf(acc.x + bb.x, 0.f);
    acc.y = fmaxf(acc.y + bb.y, 0.f);
    acc.z = fmaxf(acc.z + bb.z, 0.f);
    acc.w = fmaxf(acc.w + bb.w, 0.f);
    red_add_v4(&g_pool[b * HID2 + j * 4], acc);
    if (j == 0) atomicAdd(&g_cnt[b], 1.0f);
}

// ---------------- GEMM: fp16 m16n8k16 mma + ldmatrix, cp.async 2-stage ------
// C[M,N] = A[M,K] @ Bt[N,K]^T (+bias,relu). BM=128, BN=128, BK=32.
// 8 warps 4(m)x2(n); warp tile 32m x 64n. Stride 40 halfs (80B) -> LDSM
// row addresses hit banks {0,20,8,28,16,4,24,12}: conflict-free.
template <int KDIM, int NDIM, bool RELU_BIAS>
__device__ __forceinline__ void gemm_f16_body(const unsigned short* __restrict__ A,
                                              const unsigned short* __restrict__ Bt,
                                              const float* __restrict__ bias,
                                              unsigned short* __restrict__ C) {
    constexpr int BM = 128, BN = 128, BK = 32;
    constexpr int STR = 40;
    constexpr int KT  = KDIM / BK;
    __shared__ unsigned short As[2][BM * STR];
    __shared__ unsigned short Bs[2][BN * STR];

    const int t    = threadIdx.x;
    const int lane = t & 31;
    const int w    = t >> 5;
    const int mw   = w & 3;
    const int nw   = w >> 2;
    const int g    = lane >> 2;
    const int tg   = lane & 3;
    const int cRow = blockIdx.y * BM;
    const int cCol = blockIdx.x * BN;

    // ldmatrix lane-address selectors (constant per thread)
    const int aRowSel = lane & 15;              // row within 16-row fragment
    const int aColSel = (lane & 16) >> 1;       // 0 or 8 (k-half)
    const int bSel    = lane >> 3;              // 0..3 matrix index
    const int bRowSel = lane & 7;               // row within n8 tile
    const int bNtOff  = (bSel >> 1);            // 0/1: which nt of the pair
    const int bColSel = (bSel & 1) * 8;         // k-half

    float acc[2][8][4];
    #pragma unroll
    for (int mt = 0; mt < 2; mt++)
        #pragma unroll
        for (int nt = 0; nt < 8; nt++)
            #pragma unroll
            for (int i = 0; i < 4; i++) acc[mt][nt][i] = 0.0f;

    auto load_tile = [&](int kt, int buf) {
        int k0 = kt * BK;
        #pragma unroll
        for (int i = 0; i < 2; i++) {
            int f  = t + 256 * i;
            int r  = f >> 2;
            int ck = f & 3;
            int sz = (cRow + r < N_NODES) ? 16 : 0;
            cp_async16(&As[buf][r * STR + ck * 8],
                       A + (size_t)(cRow + r) * KDIM + k0 + ck * 8, sz);
            cp_async16(&Bs[buf][r * STR + ck * 8],
                       Bt + (size_t)(cCol + r) * KDIM + k0 + ck * 8, 16);
        }
        cp_commit();
    };

    load_tile(0, 0);
    for (int kt = 0; kt < KT; kt++) {
        if (kt + 1 < KT) { load_tile(kt + 1, (kt + 1) & 1); cp_wait<1>(); }
        else             { cp_wait<0>(); }
        __syncthreads();
        const unsigned short* as = As[kt & 1];
        const unsigned short* bs = Bs[kt & 1];
        #pragma unroll
        for (int kk = 0; kk < BK; kk += 16) {
            unsigned a[2][4];
            #pragma unroll
            for (int mt = 0; mt < 2; mt++) {
                int row = mw * 32 + mt * 16 + aRowSel;
                ldsm_x4(a[mt], &as[row * STR + kk + aColSel]);
            }
            unsigned b[8][2];
            #pragma unroll
            for (int p = 0; p < 4; p++) {
                int n = nw * 64 + (p * 2 + bNtOff) * 8 + bRowSel;
                unsigned r[4];
                ldsm_x4(r, &bs[n * STR + kk + bColSel]);
                b[p * 2][0]     = r[0];
                b[p * 2][1]     = r[1];
                b[p * 2 + 1][0] = r[2];
                b[p * 2 + 1][1] = r[3];
            }
            #pragma unroll
            for (int nt = 0; nt < 8; nt++) {
                mma_f16(acc[0][nt], a[0], b[nt]);
                mma_f16(acc[1][nt], a[1], b[nt]);
            }
        }
        __syncthreads();
    }

    #pragma unroll
    for (int mt = 0; mt < 2; mt++) {
        int rBase = cRow + mw * 32 + mt * 16 + g;
        #pragma unroll
        for (int nt = 0; nt < 8; nt++) {
            int c = cCol + nw * 64 + nt * 8 + 2 * tg;
            float f0 = acc[mt][nt][0], f1 = acc[mt][nt][1];
            float f2 = acc[mt][nt][2], f3 = acc[mt][nt][3];
            if (RELU_BIAS) {
                float2 bb = *(const float2*)(bias + c);
                f0 = fmaxf(f0 + bb.x, 0.f); f1 = fmaxf(f1 + bb.y, 0.f);
                f2 = fmaxf(f2 + bb.x, 0.f); f3 = fmaxf(f3 + bb.y, 0.f);
            }
            if (rBase < N_NODES)
                *(unsigned*)(C + (size_t)rBase * NDIM + c) = f2h2(f0, f1);
            if (rBase + 8 < N_NODES)
                *(unsigned*)(C + (size_t)(rBase + 8) * NDIM + c) = f2h2(f2, f3);
        }
    }
}

__global__ void __launch_bounds__(256) k_gemm1(const float* __restrict__ b1) {
    gemm_f16_body<IN_DIM, HID, true>(g_a1h, g_w1h, b1, g_h1h);
}

__global__ void __launch_bounds__(256) k_gemm2() {
    gemm_f16_body<HID, HID2, false>(g_h1h, g_w2h, nullptr, g_m2h);
}

// ---------------- fc tail ----------------
__global__ void k_out(const float* __restrict__ Wfc, const float* __restrict__ bfc,
                      float* __restrict__ out) {
    int t = threadIdx.x;
    if (t >= N_GRAPHS * OUT_DIM) return;
    int g = t >> 2;
    int o = t & 3;
    float inv = 1.0f / fmaxf(g_cnt[g], 1.0f);
    float s = 0.0f;
    #pragma unroll 16
    for (int k = 0; k < HID2; k++)
        s = fmaf(g_pool[g * HID2 + k], Wfc[k * OUT_DIM + o], s);
    out[t] = s * inv + bfc[o];
}

// ---------------- launch ----------------
extern "C" void kernel_launch(void* const* d_in, const int* in_sizes, int n_in,
                              void* d_out, int out_size) {
    int ix = -1, isrc = -1, idst = -1, ibatch = -1, iW1 = -1, iW2 = -1;
    int ib1 = -1, ib2 = -1, iWfc = -1, ibfc = -1;
    for (int i = 0; i < n_in; i++) {
        int s = in_sizes[i];
        if      (s == N_NODES * IN_DIM)  ix = i;
        else if (s == N_EDGES)           { if (isrc < 0) isrc = i; else idst = i; }
        else if (s == N_NODES)           ibatch = i;
        else if (s == IN_DIM * HID)      { if (iW1 < 0) iW1 = i; else iW2 = i; }
        else if (s == HID)               ib1 = i;
        else if (s == HID2)              ib2 = i;
        else if (s == HID2 * OUT_DIM)    iWfc = i;
        else if (s == OUT_DIM)           ibfc = i;
    }
    if (in_sizes[0] != N_NODES * IN_DIM) { int tmp = isrc; isrc = idst; idst = tmp; }

    const float* x     = (const float*)d_in[ix];
    const void*  src   = d_in[isrc];
    const void*  dst   = d_in[idst];
    const void*  batch = d_in[ibatch];
    const float* W1    = (const float*)d_in[iW1];
    const float* b1    = (const float*)d_in[ib1];
    const float* W2    = (const float*)d_in[iW2];
    const float* b2    = (const float*)d_in[ib2];
    const float* Wfc   = (const float*)d_in[iWfc];
    const float* bfc   = (const float*)d_in[ibfc];
    float* out = (float*)d_out;

    const int TPB = 256;
    const int edgeBlocks = (N_EDGES + TPB - 1) / TPB;
    const int nvecBlocks = (N_NODES * 32 + TPB - 1) / TPB;

    // fused setup (detect + x/weight cvt + transposes + zero)
    k_setup<<<1600, TPB>>>((const int*)src, x, W1, W2);

    // CSR build: hist -> single-kernel lookback scan -> fill
    k_hist<<<edgeBlocks, TPB>>>(dst);
    k_scan<<<SCAN_BLKS, SCAN_TPB>>>();
    k_fill<<<edgeBlocks, TPB>>>(src, dst);

    // layer 1
    k_gather1<<<nvecBlocks, TPB>>>();
    {
        dim3 grid(HID / 128, (N_NODES + 127) / 128);
        k_gemm1<<<grid, 256>>>(b1);
    }

    // layer 2 (+fused pool)
    {
        dim3 grid(HID2 / 128, (N_NODES + 127) / 128);
        k_gemm2<<<grid, 256>>>();
    }
    k_gather2<<<nvecBlocks, TPB>>>(batch, b2);

    // fc
    k_out<<<1, N_GRAPHS * OUT_DIM>>>(Wfc, bfc, out);
}

// round 16
// speedup vs baseline: 1.0477x; 1.0477x over previous
#include <cuda_runtime.h>
#include <cuda_fp16.h>

// ---------------- problem constants ----------------
#define N_NODES  50000
#define N_EDGES  640000
#define N_GRAPHS 64
#define IN_DIM   128
#define HID      256
#define HID2     128   // HID/2
#define OUT_DIM  4

#define SCAN_TPB   256
#define SCAN_BLKS  ((N_NODES + SCAN_TPB - 1) / SCAN_TPB)   // 196

// ---------------- scratch (static device arrays; no allocation) ----------------
// RULE: symbols referenced ONLY inside device code (host shadow + ATS trap).
// Indices are int32 (proven: rounds with forced-int32 vs dtype-detection gave
// bit-identical results).
__device__ float              g_dinv[N_NODES];            // rsqrt(deg+1)
__device__ int                g_count [N_NODES];          // self-cleaned by k_scan
__device__ int                g_rowptr[N_NODES + 1];
__device__ unsigned long long g_lb[SCAN_BLKS];            // lookback: state<<32 | sum
__device__ unsigned           g_epoch;                    // lookback epoch (per call)
__device__ int                g_esrc [N_EDGES];           // CSR: src per slot
__device__ int                g_eoff [N_EDGES];           // bucket-local offset
__device__ unsigned short     g_xh  [N_NODES * IN_DIM];   // x as fp16
__device__ unsigned short     g_w1h [HID  * IN_DIM];      // W1^T [256][128] fp16
__device__ unsigned short     g_w2h [HID2 * HID];         // W2^T [128][256] fp16
__device__ unsigned short     g_a1h [N_NODES * IN_DIM];   // aggregated x, fp16
__device__ unsigned short     g_h1h [N_NODES * HID];      // relu(a1@W1+b1), fp16
__device__ unsigned short     g_m2h [N_NODES * HID2];     // h1@W2, fp16
__device__ float              g_pool[N_GRAPHS * HID2];
__device__ float              g_cnt [N_GRAPHS];

// ---------------- helpers ----------------
__device__ __forceinline__ void red_add_v4(float* addr, float4 v) {
    asm volatile("red.global.add.v4.f32 [%0], {%1,%2,%3,%4};"
                 :: "l"(addr), "f"(v.x), "f"(v.y), "f"(v.z), "f"(v.w)
                 : "memory");
}

// m16n8k16 fp16 MMA, fp32 accumulate (D += A*B), row.col
__device__ __forceinline__ void mma_f16(float* d, const unsigned* a, const unsigned* b) {
    asm volatile(
        "mma.sync.aligned.m16n8k16.row.col.f32.f16.f16.f32 "
        "{%0,%1,%2,%3}, {%4,%5,%6,%7}, {%8,%9}, {%0,%1,%2,%3};"
        : "+f"(d[0]), "+f"(d[1]), "+f"(d[2]), "+f"(d[3])
        : "r"(a[0]), "r"(a[1]), "r"(a[2]), "r"(a[3]), "r"(b[0]), "r"(b[1]));
}

__device__ __forceinline__ void ldsm_x4(unsigned* r, const void* smem_addr) {
    unsigned a = (unsigned)__cvta_generic_to_shared(smem_addr);
    asm volatile("ldmatrix.sync.aligned.m8n8.x4.shared.b16 {%0,%1,%2,%3}, [%4];"
                 : "=r"(r[0]), "=r"(r[1]), "=r"(r[2]), "=r"(r[3]) : "r"(a));
}

__device__ __forceinline__ void cp_async16(void* smem, const void* gmem, int szbytes) {
    unsigned saddr = (unsigned)__cvta_generic_to_shared(smem);
    asm volatile("cp.async.cg.shared.global [%0], [%1], 16, %2;"
                 :: "r"(saddr), "l"(gmem), "r"(szbytes));
}
__device__ __forceinline__ void cp_commit() {
    asm volatile("cp.async.commit_group;");
}
template <int N>
__device__ __forceinline__ void cp_wait() {
    asm volatile("cp.async.wait_group %0;" :: "n"(N));
}

__device__ __forceinline__ float2 h2f(unsigned u) {
    __half2 h = *reinterpret_cast<__half2*>(&u);
    return __half22float2(h);
}
__device__ __forceinline__ unsigned f2h2(float a, float b) {
    __half2 h = __floats2half2_rn(a, b);
    return *reinterpret_cast<unsigned*>(&h);
}

// ---------------- fused setup: cvt x+weights, zero, epoch, HIST ------------
// g_count is zero on entry: static zero-init on first call, self-cleaned by
// k_scan on every call thereafter.
__global__ void k_setup(const float* __restrict__ x,
                        const float* __restrict__ W1, const float* __restrict__ W2,
                        const int* __restrict__ dst) {
    int tid = blockIdx.x * blockDim.x + threadIdx.x;
    int nth = gridDim.x * blockDim.x;

    if (tid == 0) g_epoch = g_epoch + 1;

    for (int i = tid; i < N_NODES * IN_DIM / 4; i += nth) {
        float4 v = ((const float4*)x)[i];
        uint2 o = make_uint2(f2h2(v.x, v.y), f2h2(v.z, v.w));
        ((uint2*)g_xh)[i] = o;
    }
    for (int i = tid; i < IN_DIM * HID; i += nth) {
        int n = i >> 7, k = i & 127;
        g_w1h[n * IN_DIM + k] = __half_as_ushort(__float2half_rn(W1[k * HID + n]));
    }
    for (int i = tid; i < HID * HID2; i += nth) {
        int n = i >> 8, k = i & 255;
        g_w2h[n * HID + k] = __half_as_ushort(__float2half_rn(W2[k * HID2 + n]));
    }
    if (tid < N_GRAPHS * HID2) g_pool[tid] = 0.0f;
    if (tid < N_GRAPHS) g_cnt[tid] = 0.0f;

    // histogram (indices int32)
    for (int e = tid; e < N_EDGES; e += nth) {
        int d = __ldg(dst + e);
        if ((unsigned)d < (unsigned)N_NODES)
            g_eoff[e] = atomicAdd(&g_count[d], 1);
    }
}

// ---------------- single-kernel epoch-tagged decoupled-lookback scan --------
// rowptr = exclusive scan of count; dinv = rsqrt(count+1); count self-cleaned.
__global__ void __launch_bounds__(SCAN_TPB) k_scan() {
    __shared__ int sh[SCAN_TPB];
    __shared__ int s_excl;
    int b = blockIdx.x;
    int t = threadIdx.x;
    int i = b * SCAN_TPB + t;
    unsigned ep = g_epoch;
    const unsigned ST_PART = 2u * ep;
    const unsigned ST_FULL = 2u * ep + 1u;

    int c = (i < N_NODES) ? g_count[i] : 0;
    if (i < N_NODES) g_count[i] = 0;            // self-clean for next call
    sh[t] = c;
    __syncthreads();
    for (int d = 1; d < SCAN_TPB; d <<= 1) {
        int u = (t >= d) ? sh[t - d] : 0;
        __syncthreads();
        sh[t] += u;
        __syncthreads();
    }
    int aggregate = sh[SCAN_TPB - 1];
    if (t == 0) {
        if (b == 0) {
            atomicExch(&g_lb[0], ((unsigned long long)ST_FULL << 32) | (unsigned)aggregate);
            s_excl = 0;
        } else {
            atomicExch(&g_lb[b], ((unsigned long long)ST_PART << 32) | (unsigned)aggregate);
            int excl = 0;
            for (int j = b - 1; j >= 0; j--) {
                unsigned long long v;
                unsigned st;
                do {
                    v = atomicAdd(&g_lb[j], 0ull);
                    st = (unsigned)(v >> 32);
                } while (st < ST_PART);
                excl += (int)(unsigned)v;
                if (st == ST_FULL) break;
            }
            atomicExch(&g_lb[b], ((unsigned long long)ST_FULL << 32) | (unsigned)(excl + aggregate));
            s_excl = excl;
        }
    }
    __syncthreads();
    if (i < N_NODES) {
        g_rowptr[i] = s_excl + sh[t] - c;
        g_dinv[i]   = rsqrtf((float)c + 1.0f);
    }
    if (b == 0 && t == 0) g_rowptr[N_NODES] = N_EDGES;
}

// atomic-free fill: ONE scattered 4B store per edge (norm computed in gather)
__global__ void k_fill(const int* __restrict__ src, const int* __restrict__ dst) {
    int e = blockIdx.x * blockDim.x + threadIdx.x;
    if (e >= N_EDGES) return;
    int s = __ldg(src + e);
    int d = __ldg(dst + e);
    if ((unsigned)s >= (unsigned)N_NODES || (unsigned)d >= (unsigned)N_NODES) return;
    g_esrc[g_rowptr[d] + g_eoff[e]] = s;
}

// ---------------- gather core (fp16 features, fp32 acc, norm on the fly) ---
// One warp per destination node; lane j owns 4 features (uint2 = 4 halfs).
// w_k = dinv[src_k] * dinv[d]; dinv is L1-resident, warp-uniform broadcast.
__device__ __forceinline__ float4 gather_acc(const uint2* __restrict__ ft, int wid, int j) {
    float di = g_dinv[wid];
    uint2 u0 = ft[(size_t)wid * 32 + j];
    float2 p0 = h2f(u0.x), p1 = h2f(u0.y);
    float s2 = di * di;
    float4 acc = make_float4(p0.x * s2, p0.y * s2, p1.x * s2, p1.y * s2);

    int i   = g_rowptr[wid];
    int end = g_rowptr[wid + 1];
    for (; i + 3 < end; i += 4) {
        int s0 = __ldg(&g_esrc[i]),     s1 = __ldg(&g_esrc[i + 1]);
        int s2i = __ldg(&g_esrc[i + 2]), s3 = __ldg(&g_esrc[i + 3]);
        float w0 = __ldg(&g_dinv[s0]) * di, w1 = __ldg(&g_dinv[s1]) * di;
        float w2 = __ldg(&g_dinv[s2i]) * di, w3 = __ldg(&g_dinv[s3]) * di;
        uint2 ua = ft[(size_t)s0 * 32 + j];
        uint2 ub = ft[(size_t)s1 * 32 + j];
        uint2 uc = ft[(size_t)s2i * 32 + j];
        uint2 ud = ft[(size_t)s3 * 32 + j];
        float2 a0 = h2f(ua.x), a1 = h2f(ua.y);
        float2 b0 = h2f(ub.x), b1 = h2f(ub.y);
        float2 c0 = h2f(uc.x), c1 = h2f(uc.y);
        float2 d0 = h2f(ud.x), d1 = h2f(ud.y);
        acc.x += w0 * a0.x + w1 * b0.x + w2 * c0.x + w3 * d0.x;
        acc.y += w0 * a0.y + w1 * b0.y + w2 * c0.y + w3 * d0.y;
        acc.z += w0 * a1.x + w1 * b1.x + w2 * c1.x + w3 * d1.x;
        acc.w += w0 * a1.y + w1 * b1.y + w2 * c1.y + w3 * d1.y;
    }
    for (; i < end; i++) {
        int s0 = __ldg(&g_esrc[i]);
        float w0 = __ldg(&g_dinv[s0]) * di;
        uint2 ua = ft[(size_t)s0 * 32 + j];
        float2 a0 = h2f(ua.x), a1 = h2f(ua.y);
        acc.x += w0 * a0.x; acc.y += w0 * a0.y;
        acc.z += w0 * a1.x; acc.w += w0 * a1.y;
    }
    return acc;
}

__global__ void k_gather1() {
    int wid = (blockIdx.x * blockDim.x + threadIdx.x) >> 5;
    if (wid >= N_NODES) return;
    int j = threadIdx.x & 31;
    float4 acc = gather_acc((const uint2*)g_xh, wid, j);
    ((uint2*)g_a1h)[(size_t)wid * 32 + j] =
        make_uint2(f2h2(acc.x, acc.y), f2h2(acc.z, acc.w));
}

// gather2 + fused pooling: pool[batch[d]] += relu(agg2[d] + b2)
__global__ void k_gather2(const int* __restrict__ batch, const float* __restrict__ b2) {
    int wid = (blockIdx.x * blockDim.x + threadIdx.x) >> 5;
    if (wid >= N_NODES) return;
    int j = threadIdx.x & 31;
    float4 acc = gather_acc((const uint2*)g_m2h, wid, j);

    int b = __ldg(batch + wid);
    if ((unsigned)b >= (unsigned)N_GRAPHS) return;
    float4 bb = ((const float4*)b2)[j];
    acc.x = fmaxf(acc.x + bb.x, 0.f);
    acc.y = fmaxf(acc.y + bb.y, 0.f);
    acc.z = fmaxf(acc.z + bb.z, 0.f);
    acc.w = fmaxf(acc.w + bb.w, 0.f);
    red_add_v4(&g_pool[b * HID2 + j * 4], acc);
    if (j == 0) atomicAdd(&g_cnt[b], 1.0f);
}

// ---------------- GEMM: fp16 m16n8k16 mma + ldmatrix, cp.async 2-stage ------
// C[M,N] = A[M,K] @ Bt[N,K]^T (+bias,relu). BM=128, BN=128, BK=32.
// 8 warps 4(m)x2(n); warp tile 32m x 64n. Stride 40 halfs (80B) -> conflict-free.
template <int KDIM, int NDIM, bool RELU_BIAS>
__device__ __forceinline__ void gemm_f16_body(const unsigned short* __restrict__ A,
                                              const unsigned short* __restrict__ Bt,
                                              const float* __restrict__ bias,
                                              unsigned short* __restrict__ C) {
    constexpr int BM = 128, BN = 128, BK = 32;
    constexpr int STR = 40;
    constexpr int KT  = KDIM / BK;
    __shared__ unsigned short As[2][BM * STR];
    __shared__ unsigned short Bs[2][BN * STR];

    const int t    = threadIdx.x;
    const int lane = t & 31;
    const int w    = t >> 5;
    const int mw   = w & 3;
    const int nw   = w >> 2;
    const int g    = lane >> 2;
    const int tg   = lane & 3;
    const int cRow = blockIdx.y * BM;
    const int cCol = blockIdx.x * BN;

    const int aRowSel = lane & 15;
    const int aColSel = (lane & 16) >> 1;
    const int bSel    = lane >> 3;
    const int bRowSel = lane & 7;
    const int bNtOff  = (bSel >> 1);
    const int bColSel = (bSel & 1) * 8;

    float acc[2][8][4];
    #pragma unroll
    for (int mt = 0; mt < 2; mt++)
        #pragma unroll
        for (int nt = 0; nt < 8; nt++)
            #pragma unroll
            for (int i = 0; i < 4; i++) acc[mt][nt][i] = 0.0f;

    auto load_tile = [&](int kt, int buf) {
        int k0 = kt * BK;
        #pragma unroll
        for (int i = 0; i < 2; i++) {
            int f  = t + 256 * i;
            int r  = f >> 2;
            int ck = f & 3;
            int sz = (cRow + r < N_NODES) ? 16 : 0;
            cp_async16(&As[buf][r * STR + ck * 8],
                       A + (size_t)(cRow + r) * KDIM + k0 + ck * 8, sz);
            cp_async16(&Bs[buf][r * STR + ck * 8],
                       Bt + (size_t)(cCol + r) * KDIM + k0 + ck * 8, 16);
        }
        cp_commit();
    };

    load_tile(0, 0);
    for (int kt = 0; kt < KT; kt++) {
        if (kt + 1 < KT) { load_tile(kt + 1, (kt + 1) & 1); cp_wait<1>(); }
        else             { cp_wait<0>(); }
        __syncthreads();
        const unsigned short* as = As[kt & 1];
        const unsigned short* bs = Bs[kt & 1];
        #pragma unroll
        for (int kk = 0; kk < BK; kk += 16) {
            unsigned a[2][4];
            #pragma unroll
            for (int mt = 0; mt < 2; mt++) {
                int row = mw * 32 + mt * 16 + aRowSel;
                ldsm_x4(a[mt], &as[row * STR + kk + aColSel]);
            }
            unsigned b[8][2];
            #pragma unroll
            for (int p = 0; p < 4; p++) {
                int n = nw * 64 + (p * 2 + bNtOff) * 8 + bRowSel;
                unsigned r[4];
                ldsm_x4(r, &bs[n * STR + kk + bColSel]);
                b[p * 2][0]     = r[0];
                b[p * 2][1]     = r[1];
                b[p * 2 + 1][0] = r[2];
                b[p * 2 + 1][1] = r[3];
            }
            #pragma unroll
            for (int nt = 0; nt < 8; nt++) {
                mma_f16(acc[0][nt], a[0], b[nt]);
                mma_f16(acc[1][nt], a[1], b[nt]);
            }
        }
        __syncthreads();
    }

    #pragma unroll
    for (int mt = 0; mt < 2; mt++) {
        int rBase = cRow + mw * 32 + mt * 16 + g;
        #pragma unroll
        for (int nt = 0; nt < 8; nt++) {
            int c = cCol + nw * 64 + nt * 8 + 2 * tg;
            float f0 = acc[mt][nt][0], f1 = acc[mt][nt][1];
            float f2 = acc[mt][nt][2], f3 = acc[mt][nt][3];
            if (RELU_BIAS) {
                float2 bb = *(const float2*)(bias + c);
                f0 = fmaxf(f0 + bb.x, 0.f); f1 = fmaxf(f1 + bb.y, 0.f);
                f2 = fmaxf(f2 + bb.x, 0.f); f3 = fmaxf(f3 + bb.y, 0.f);
            }
            if (rBase < N_NODES)
                *(unsigned*)(C + (size_t)rBase * NDIM + c) = f2h2(f0, f1);
            if (rBase + 8 < N_NODES)
                *(unsigned*)(C + (size_t)(rBase + 8) * NDIM + c) = f2h2(f2, f3);
        }
    }
}

__global__ void __launch_bounds__(256) k_gemm1(const float* __restrict__ b1) {
    gemm_f16_body<IN_DIM, HID, true>(g_a1h, g_w1h, b1, g_h1h);
}

__global__ void __launch_bounds__(256) k_gemm2() {
    gemm_f16_body<HID, HID2, false>(g_h1h, g_w2h, nullptr, g_m2h);
}

// ---------------- fc tail ----------------
__global__ void k_out(const float* __restrict__ Wfc, const float* __restrict__ bfc,
                      float* __restrict__ out) {
    int t = threadIdx.x;
    if (t >= N_GRAPHS * OUT_DIM) return;
    int g = t >> 2;
    int o = t & 3;
    float inv = 1.0f / fmaxf(g_cnt[g], 1.0f);
    float s = 0.0f;
    #pragma unroll 16
    for (int k = 0; k < HID2; k++)
        s = fmaf(g_pool[g * HID2 + k], Wfc[k * OUT_DIM + o], s);
    out[t] = s * inv + bfc[o];
}

// ---------------- launch ----------------
extern "C" void kernel_launch(void* const* d_in, const int* in_sizes, int n_in,
                              void* d_out, int out_size) {
    int ix = -1, isrc = -1, idst = -1, ibatch = -1, iW1 = -1, iW2 = -1;
    int ib1 = -1, ib2 = -1, iWfc = -1, ibfc = -1;
    for (int i = 0; i < n_in; i++) {
        int s = in_sizes[i];
        if      (s == N_NODES * IN_DIM)  ix = i;
        else if (s == N_EDGES)           { if (isrc < 0) isrc = i; else idst = i; }
        else if (s == N_NODES)           ibatch = i;
        else if (s == IN_DIM * HID)      { if (iW1 < 0) iW1 = i; else iW2 = i; }
        else if (s == HID)               ib1 = i;
        else if (s == HID2)              ib2 = i;
        else if (s == HID2 * OUT_DIM)    iWfc = i;
        else if (s == OUT_DIM)           ibfc = i;
    }
    if (in_sizes[0] != N_NODES * IN_DIM) { int tmp = isrc; isrc = idst; idst = tmp; }

    const float* x     = (const float*)d_in[ix];
    const int*   src   = (const int*)  d_in[isrc];
    const int*   dst   = (const int*)  d_in[idst];
    const int*   batch = (const int*)  d_in[ibatch];
    const float* W1    = (const float*)d_in[iW1];
    const float* b1    = (const float*)d_in[ib1];
    const float* W2    = (const float*)d_in[iW2];
    const float* b2    = (const float*)d_in[ib2];
    const float* Wfc   = (const float*)d_in[iWfc];
    const float* bfc   = (const float*)d_in[ibfc];
    float* out = (float*)d_out;

    const int TPB = 256;
    const int edgeBlocks = (N_EDGES + TPB - 1) / TPB;
    const int nvecBlocks = (N_NODES * 32 + TPB - 1) / TPB;

    // fused setup (cvt + zero + epoch + histogram)
    k_setup<<<1600, TPB>>>(x, W1, W2, dst);

    // CSR: epoch-lookback scan (self-cleaning counts) -> single-store fill
    k_scan<<<SCAN_BLKS, SCAN_TPB>>>();
    k_fill<<<edgeBlocks, TPB>>>(src, dst);

    // layer 1
    k_gather1<<<nvecBlocks, TPB>>>();
    {
        dim3 grid(HID / 128, (N_NODES + 127) / 128);
        k_gemm1<<<grid, 256>>>(b1);
    }

    // layer 2 (+fused pool)
    {
        dim3 grid(HID2 / 128, (N_NODES + 127) / 128);
        k_gemm2<<<grid, 256>>>();
    }
    k_gather2<<<nvecBlocks, TPB>>>(batch, b2);

    // fc
    k_out<<<1, N_GRAPHS * OUT_DIM>>>(Wfc, bfc, out);
}

// round 17
// speedup vs baseline: 1.0760x; 1.0270x over previous
#include <cuda_runtime.h>
#include <cuda_fp16.h>

// ---------------- problem constants ----------------
#define N_NODES  50000
#define N_EDGES  640000
#define N_GRAPHS 64
#define IN_DIM   128
#define HID      256
#define HID2     128   // HID/2
#define OUT_DIM  4

#define SCAN_TPB   256
#define SCAN_BLKS  ((N_NODES + SCAN_TPB - 1) / SCAN_TPB)   // 196

// ---------------- scratch (static device arrays; no allocation) ----------------
// RULE: symbols referenced ONLY inside device code (host shadow + ATS trap).
// Indices are int32 (proven earlier by bit-identical outputs).
__device__ float              g_dinv[N_NODES];            // rsqrt(deg+1)
__device__ int                g_count [N_NODES];          // self-cleaned by k_scan
__device__ int                g_rowptr[N_NODES + 1];
__device__ unsigned long long g_lb[SCAN_BLKS];            // lookback: state<<32 | sum
__device__ unsigned           g_epoch;                    // lookback epoch (per call)
__device__ int                g_esrc [N_EDGES];           // CSR: src per slot
__device__ int                g_eoff [N_EDGES];           // bucket-local offset
__device__ unsigned short     g_w1h [HID  * IN_DIM];      // W1^T [256][128] fp16
__device__ unsigned short     g_w2h [HID2 * HID];         // W2^T [128][256] fp16
__device__ unsigned short     g_a1h [N_NODES * IN_DIM];   // aggregated x, fp16 (GEMM1 in)
__device__ unsigned short     g_h1h [N_NODES * HID];      // relu(a1@W1+b1), fp16 (GEMM2 in)
__device__ float4             g_m2f [N_NODES * (HID2/4)]; // h1@W2, fp32 (gather2 in)
__device__ float              g_pool[N_GRAPHS * HID2];
__device__ float              g_cnt [N_GRAPHS];

// ---------------- helpers ----------------
__device__ __forceinline__ void red_add_v4(float* addr, float4 v) {
    asm volatile("red.global.add.v4.f32 [%0], {%1,%2,%3,%4};"
                 :: "l"(addr), "f"(v.x), "f"(v.y), "f"(v.z), "f"(v.w)
                 : "memory");
}

// m16n8k16 fp16 MMA, fp32 accumulate (D += A*B), row.col
__device__ __forceinline__ void mma_f16(float* d, const unsigned* a, const unsigned* b) {
    asm volatile(
        "mma.sync.aligned.m16n8k16.row.col.f32.f16.f16.f32 "
        "{%0,%1,%2,%3}, {%4,%5,%6,%7}, {%8,%9}, {%0,%1,%2,%3};"
        : "+f"(d[0]), "+f"(d[1]), "+f"(d[2]), "+f"(d[3])
        : "r"(a[0]), "r"(a[1]), "r"(a[2]), "r"(a[3]), "r"(b[0]), "r"(b[1]));
}

__device__ __forceinline__ void ldsm_x4(unsigned* r, const void* smem_addr) {
    unsigned a = (unsigned)__cvta_generic_to_shared(smem_addr);
    asm volatile("ldmatrix.sync.aligned.m8n8.x4.shared.b16 {%0,%1,%2,%3}, [%4];"
                 : "=r"(r[0]), "=r"(r[1]), "=r"(r[2]), "=r"(r[3]) : "r"(a));
}

__device__ __forceinline__ void cp_async16(void* smem, const void* gmem, int szbytes) {
    unsigned saddr = (unsigned)__cvta_generic_to_shared(smem);
    asm volatile("cp.async.cg.shared.global [%0], [%1], 16, %2;"
                 :: "r"(saddr), "l"(gmem), "r"(szbytes));
}
__device__ __forceinline__ void cp_commit() {
    asm volatile("cp.async.commit_group;");
}
template <int N>
__device__ __forceinline__ void cp_wait() {
    asm volatile("cp.async.wait_group %0;" :: "n"(N));
}

__device__ __forceinline__ unsigned f2h2(float a, float b) {
    __half2 h = __floats2half2_rn(a, b);
    return *reinterpret_cast<unsigned*>(&h);
}

// ---------------- fused setup: cvt weights, zero, epoch, HIST ------------
// g_count is zero on entry: static zero-init on first call, self-cleaned by
// k_scan on every call thereafter.
__global__ void k_setup(const float* __restrict__ W1, const float* __restrict__ W2,
                        const int* __restrict__ dst) {
    int tid = blockIdx.x * blockDim.x + threadIdx.x;
    int nth = gridDim.x * blockDim.x;

    if (tid == 0) g_epoch = g_epoch + 1;

    for (int i = tid; i < IN_DIM * HID; i += nth) {
        int n = i >> 7, k = i & 127;
        g_w1h[n * IN_DIM + k] = __half_as_ushort(__float2half_rn(W1[k * HID + n]));
    }
    for (int i = tid; i < HID * HID2; i += nth) {
        int n = i >> 8, k = i & 255;
        g_w2h[n * HID + k] = __half_as_ushort(__float2half_rn(W2[k * HID2 + n]));
    }
    if (tid < N_GRAPHS * HID2) g_pool[tid] = 0.0f;
    if (tid < N_GRAPHS) g_cnt[tid] = 0.0f;

    // histogram (indices int32)
    for (int e = tid; e < N_EDGES; e += nth) {
        int d = __ldg(dst + e);
        if ((unsigned)d < (unsigned)N_NODES)
            g_eoff[e] = atomicAdd(&g_count[d], 1);
    }
}

// ---------------- single-kernel epoch-tagged decoupled-lookback scan --------
__global__ void __launch_bounds__(SCAN_TPB) k_scan() {
    __shared__ int sh[SCAN_TPB];
    __shared__ int s_excl;
    int b = blockIdx.x;
    int t = threadIdx.x;
    int i = b * SCAN_TPB + t;
    unsigned ep = g_epoch;
    const unsigned ST_PART = 2u * ep;
    const unsigned ST_FULL = 2u * ep + 1u;

    int c = (i < N_NODES) ? g_count[i] : 0;
    if (i < N_NODES) g_count[i] = 0;            // self-clean for next call
    sh[t] = c;
    __syncthreads();
    for (int d = 1; d < SCAN_TPB; d <<= 1) {
        int u = (t >= d) ? sh[t - d] : 0;
        __syncthreads();
        sh[t] += u;
        __syncthreads();
    }
    int aggregate = sh[SCAN_TPB - 1];
    if (t == 0) {
        if (b == 0) {
            atomicExch(&g_lb[0], ((unsigned long long)ST_FULL << 32) | (unsigned)aggregate);
            s_excl = 0;
        } else {
            atomicExch(&g_lb[b], ((unsigned long long)ST_PART << 32) | (unsigned)aggregate);
            int excl = 0;
            for (int j = b - 1; j >= 0; j--) {
                unsigned long long v;
                unsigned st;
                do {
                    v = atomicAdd(&g_lb[j], 0ull);
                    st = (unsigned)(v >> 32);
                } while (st < ST_PART);
                excl += (int)(unsigned)v;
                if (st == ST_FULL) break;
            }
            atomicExch(&g_lb[b], ((unsigned long long)ST_FULL << 32) | (unsigned)(excl + aggregate));
            s_excl = excl;
        }
    }
    __syncthreads();
    if (i < N_NODES) {
        g_rowptr[i] = s_excl + sh[t] - c;
        g_dinv[i]   = rsqrtf((float)c + 1.0f);
    }
    if (b == 0 && t == 0) g_rowptr[N_NODES] = N_EDGES;
}

// atomic-free fill: ONE scattered 4B store per edge
__global__ void k_fill(const int* __restrict__ src, const int* __restrict__ dst) {
    int e = blockIdx.x * blockDim.x + threadIdx.x;
    if (e >= N_EDGES) return;
    int s = __ldg(src + e);
    int d = __ldg(dst + e);
    if ((unsigned)s >= (unsigned)N_NODES || (unsigned)d >= (unsigned)N_NODES) return;
    g_esrc[g_rowptr[d] + g_eoff[e]] = s;
}

// ---------------- gather core (fp32 features, convert-free hot loop) -------
// One warp per destination node; lane j owns float4 (4 features).
__device__ __forceinline__ float4 gather_acc_f32(const float4* __restrict__ ft,
                                                 int wid, int j) {
    float di = g_dinv[wid];
    float4 v0 = ft[(size_t)wid * 32 + j];
    float s2 = di * di;
    float4 acc = make_float4(v0.x * s2, v0.y * s2, v0.z * s2, v0.w * s2);

    int i   = g_rowptr[wid];
    int end = g_rowptr[wid + 1];
    for (; i + 3 < end; i += 4) {
        int s0 = __ldg(&g_esrc[i]),      s1 = __ldg(&g_esrc[i + 1]);
        int s2i = __ldg(&g_esrc[i + 2]), s3 = __ldg(&g_esrc[i + 3]);
        float w0 = __ldg(&g_dinv[s0]) * di,  w1 = __ldg(&g_dinv[s1]) * di;
        float w2 = __ldg(&g_dinv[s2i]) * di, w3 = __ldg(&g_dinv[s3]) * di;
        float4 a = ft[(size_t)s0 * 32 + j];
        float4 b = ft[(size_t)s1 * 32 + j];
        float4 c = ft[(size_t)s2i * 32 + j];
        float4 d = ft[(size_t)s3 * 32 + j];
        acc.x += w0 * a.x + w1 * b.x + w2 * c.x + w3 * d.x;
        acc.y += w0 * a.y + w1 * b.y + w2 * c.y + w3 * d.y;
        acc.z += w0 * a.z + w1 * b.z + w2 * c.z + w3 * d.z;
        acc.w += w0 * a.w + w1 * b.w + w2 * c.w + w3 * d.w;
    }
    for (; i < end; i++) {
        int s0 = __ldg(&g_esrc[i]);
        float w0 = __ldg(&g_dinv[s0]) * di;
        float4 a = ft[(size_t)s0 * 32 + j];
        acc.x += w0 * a.x; acc.y += w0 * a.y;
        acc.z += w0 * a.z; acc.w += w0 * a.w;
    }
    return acc;
}

// gather1: reads x (fp32 input directly), writes fp16 for GEMM1
__global__ void k_gather1(const float4* __restrict__ x) {
    int wid = (blockIdx.x * blockDim.x + threadIdx.x) >> 5;
    if (wid >= N_NODES) return;
    int j = threadIdx.x & 31;
    float4 acc = gather_acc_f32(x, wid, j);
    ((uint2*)g_a1h)[(size_t)wid * 32 + j] =
        make_uint2(f2h2(acc.x, acc.y), f2h2(acc.z, acc.w));
}

// gather2 + fused pooling: reads m2 (fp32), pool[batch[d]] += relu(agg2 + b2)
__global__ void k_gather2(const int* __restrict__ batch, const float* __restrict__ b2) {
    int wid = (blockIdx.x * blockDim.x + threadIdx.x) >> 5;
    if (wid >= N_NODES) return;
    int j = threadIdx.x & 31;
    float4 acc = gather_acc_f32(g_m2f, wid, j);

    int b = __ldg(batch + wid);
    if ((unsigned)b >= (unsigned)N_GRAPHS) return;
    float4 bb = ((const float4*)b2)[j];
    acc.x = fmaxf(acc.x + bb.x, 0.f);
    acc.y = fmaxf(acc.y + bb.y, 0.f);
    acc.z = fmaxf(acc.z + bb.z, 0.f);
    acc.w = fmaxf(acc.w + bb.w, 0.f);
    red_add_v4(&g_pool[b * HID2 + j * 4], acc);
    if (j == 0) atomicAdd(&g_cnt[b], 1.0f);
}

// ---------------- GEMM: fp16 m16n8k16 mma + ldmatrix, cp.async 2-stage ------
// C[M,N] = A[M,K] @ Bt[N,K]^T (+bias,relu). BM=128, BN=128, BK=32.
// OUT_F32: epilogue writes fp32 (for m2 -> gather2); else fp16.
template <int KDIM, int NDIM, bool RELU_BIAS, bool OUT_F32>
__device__ __forceinline__ void gemm_f16_body(const unsigned short* __restrict__ A,
                                              const unsigned short* __restrict__ Bt,
                                              const float* __restrict__ bias,
                                              void* __restrict__ Cout) {
    constexpr int BM = 128, BN = 128, BK = 32;
    constexpr int STR = 40;
    constexpr int KT  = KDIM / BK;
    __shared__ unsigned short As[2][BM * STR];
    __shared__ unsigned short Bs[2][BN * STR];

    const int t    = threadIdx.x;
    const int lane = t & 31;
    const int w    = t >> 5;
    const int mw   = w & 3;
    const int nw   = w >> 2;
    const int g    = lane >> 2;
    const int tg   = lane & 3;
    const int cRow = blockIdx.y * BM;
    const int cCol = blockIdx.x * BN;

    const int aRowSel = lane & 15;
    const int aColSel = (lane & 16) >> 1;
    const int bSel    = lane >> 3;
    const int bRowSel = lane & 7;
    const int bNtOff  = (bSel >> 1);
    const int bColSel = (bSel & 1) * 8;

    float acc[2][8][4];
    #pragma unroll
    for (int mt = 0; mt < 2; mt++)
        #pragma unroll
        for (int nt = 0; nt < 8; nt++)
            #pragma unroll
            for (int i = 0; i < 4; i++) acc[mt][nt][i] = 0.0f;

    auto load_tile = [&](int kt, int buf) {
        int k0 = kt * BK;
        #pragma unroll
        for (int i = 0; i < 2; i++) {
            int f  = t + 256 * i;
            int r  = f >> 2;
            int ck = f & 3;
            int sz = (cRow + r < N_NODES) ? 16 : 0;
            cp_async16(&As[buf][r * STR + ck * 8],
                       A + (size_t)(cRow + r) * KDIM + k0 + ck * 8, sz);
            cp_async16(&Bs[buf][r * STR + ck * 8],
                       Bt + (size_t)(cCol + r) * KDIM + k0 + ck * 8, 16);
        }
        cp_commit();
    };

    load_tile(0, 0);
    for (int kt = 0; kt < KT; kt++) {
        if (kt + 1 < KT) { load_tile(kt + 1, (kt + 1) & 1); cp_wait<1>(); }
        else             { cp_wait<0>(); }
        __syncthreads();
        const unsigned short* as = As[kt & 1];
        const unsigned short* bs = Bs[kt & 1];
        #pragma unroll
        for (int kk = 0; kk < BK; kk += 16) {
            unsigned a[2][4];
            #pragma unroll
            for (int mt = 0; mt < 2; mt++) {
                int row = mw * 32 + mt * 16 + aRowSel;
                ldsm_x4(a[mt], &as[row * STR + kk + aColSel]);
            }
            unsigned b[8][2];
            #pragma unroll
            for (int p = 0; p < 4; p++) {
                int n = nw * 64 + (p * 2 + bNtOff) * 8 + bRowSel;
                unsigned r[4];
                ldsm_x4(r, &bs[n * STR + kk + bColSel]);
                b[p * 2][0]     = r[0];
                b[p * 2][1]     = r[1];
                b[p * 2 + 1][0] = r[2];
                b[p * 2 + 1][1] = r[3];
            }
            #pragma unroll
            for (int nt = 0; nt < 8; nt++) {
                mma_f16(acc[0][nt], a[0], b[nt]);
                mma_f16(acc[1][nt], a[1], b[nt]);
            }
        }
        __syncthreads();
    }

    #pragma unroll
    for (int mt = 0; mt < 2; mt++) {
        int rBase = cRow + mw * 32 + mt * 16 + g;
        #pragma unroll
        for (int nt = 0; nt < 8; nt++) {
            int c = cCol + nw * 64 + nt * 8 + 2 * tg;
            float f0 = acc[mt][nt][0], f1 = acc[mt][nt][1];
            float f2 = acc[mt][nt][2], f3 = acc[mt][nt][3];
            if (RELU_BIAS) {
                float2 bb = *(const float2*)(bias + c);
                f0 = fmaxf(f0 + bb.x, 0.f); f1 = fmaxf(f1 + bb.y, 0.f);
                f2 = fmaxf(f2 + bb.x, 0.f); f3 = fmaxf(f3 + bb.y, 0.f);
            }
            if (OUT_F32) {
                float* C = (float*)Cout;
                if (rBase < N_NODES)
                    *(float2*)(C + (size_t)rBase * NDIM + c) = make_float2(f0, f1);
                if (rBase + 8 < N_NODES)
                    *(float2*)(C + (size_t)(rBase + 8) * NDIM + c) = make_float2(f2, f3);
            } else {
                unsigned short* C = (unsigned short*)Cout;
                if (rBase < N_NODES)
                    *(unsigned*)(C + (size_t)rBase * NDIM + c) = f2h2(f0, f1);
                if (rBase + 8 < N_NODES)
                    *(unsigned*)(C + (size_t)(rBase + 8) * NDIM + c) = f2h2(f2, f3);
            }
        }
    }
}

__global__ void __launch_bounds__(256) k_gemm1(const float* __restrict__ b1) {
    gemm_f16_body<IN_DIM, HID, true, false>(g_a1h, g_w1h, b1, g_h1h);
}

__global__ void __launch_bounds__(256) k_gemm2() {
    gemm_f16_body<HID, HID2, false, true>(g_h1h, g_w2h, nullptr, (float*)g_m2f);
}

// ---------------- fc tail ----------------
__global__ void k_out(const float* __restrict__ Wfc, const float* __restrict__ bfc,
                      float* __restrict__ out) {
    int t = threadIdx.x;
    if (t >= N_GRAPHS * OUT_DIM) return;
    int g = t >> 2;
    int o = t & 3;
    float inv = 1.0f / fmaxf(g_cnt[g], 1.0f);
    float s = 0.0f;
    #pragma unroll 16
    for (int k = 0; k < HID2; k++)
        s = fmaf(g_pool[g * HID2 + k], Wfc[k * OUT_DIM + o], s);
    out[t] = s * inv + bfc[o];
}

// ---------------- launch ----------------
extern "C" void kernel_launch(void* const* d_in, const int* in_sizes, int n_in,
                              void* d_out, int out_size) {
    int ix = -1, isrc = -1, idst = -1, ibatch = -1, iW1 = -1, iW2 = -1;
    int ib1 = -1, ib2 = -1, iWfc = -1, ibfc = -1;
    for (int i = 0; i < n_in; i++) {
        int s = in_sizes[i];
        if      (s == N_NODES * IN_DIM)  ix = i;
        else if (s == N_EDGES)           { if (isrc < 0) isrc = i; else idst = i; }
        else if (s == N_NODES)           ibatch = i;
        else if (s == IN_DIM * HID)      { if (iW1 < 0) iW1 = i; else iW2 = i; }
        else if (s == HID)               ib1 = i;
        else if (s == HID2)              ib2 = i;
        else if (s == HID2 * OUT_DIM)    iWfc = i;
        else if (s == OUT_DIM)           ibfc = i;
    }
    if (in_sizes[0] != N_NODES * IN_DIM) { int tmp = isrc; isrc = idst; idst = tmp; }

    const float* x     = (const float*)d_in[ix];
    const int*   src   = (const int*)  d_in[isrc];
    const int*   dst   = (const int*)  d_in[idst];
    const int*   batch = (const int*)  d_in[ibatch];
    const float* W1    = (const float*)d_in[iW1];
    const float* b1    = (const float*)d_in[ib1];
    const float* W2    = (const float*)d_in[iW2];
    const float* b2    = (const float*)d_in[ib2];
    const float* Wfc   = (const float*)d_in[iWfc];
    const float* bfc   = (const float*)d_in[ibfc];
    float* out = (float*)d_out;

    const int TPB = 256;
    const int edgeBlocks = (N_EDGES + TPB - 1) / TPB;
    const int nvecBlocks = (N_NODES * 32 + TPB - 1) / TPB;

    // fused setup (weight cvt + zero + epoch + histogram)
    k_setup<<<1600, TPB>>>(W1, W2, dst);

    // CSR: epoch-lookback scan (self-cleaning counts) -> single-store fill
    k_scan<<<SCAN_BLKS, SCAN_TPB>>>();
    k_fill<<<edgeBlocks, TPB>>>(src, dst);

    // layer 1: gather x (fp32) -> fp16, GEMM1 (+bias,relu) -> fp16
    k_gather1<<<nvecBlocks, TPB>>>((const float4*)x);
    {
        dim3 grid(HID / 128, (N_NODES + 127) / 128);
        k_gemm1<<<grid, 256>>>(b1);
    }

    // layer 2: GEMM2 -> fp32 m2, gather2 (+fused pool)
    {
        dim3 grid(HID2 / 128, (N_NODES + 127) / 128);
        k_gemm2<<<grid, 256>>>();
    }
    k_gather2<<<nvecBlocks, TPB>>>(batch, b2);

    // fc
    k_out<<<1, N_GRAPHS * OUT_DIM>>>(Wfc, bfc, out);
}